// round 1
// baseline (speedup 1.0000x reference)
#include <cuda_runtime.h>
#include <cuda_bf16.h>

#define NU 100000
#define NI 50000
#define NT 150000          // NU + NI
#define EE 4000000
#define DD 64
#define BB 4096
#define KH 3

// ---- scratch (device globals: allocation-free) ----
__device__ __align__(256) float g_emb0[NT * DD];
__device__ __align__(256) float g_emb1[NT * DD];
__device__ __align__(256) float g_acc [NT * DD];
__device__ __align__(256) float g_dis [NT];
__device__ __align__(256) int   g_deg [NT];

__global__ void k_zero_deg() {
    int i = blockIdx.x * blockDim.x + threadIdx.x;
    if (i < NT) g_deg[i] = 0;
}

__global__ void k_hist(const int* __restrict__ row) {
    int e = blockIdx.x * blockDim.x + threadIdx.x;
    if (e < EE) atomicAdd(&g_deg[row[e]], 1);
}

__global__ void k_dis() {
    int i = blockIdx.x * blockDim.x + threadIdx.x;
    if (i < NT) {
        int d = g_deg[i];
        g_dis[i] = (d > 0) ? rsqrtf((float)d) : 0.0f;
    }
}

// init emb0 = concat(users, items); acc = emb0
__global__ void k_init(const float4* __restrict__ users,
                       const float4* __restrict__ items) {
    int i = blockIdx.x * blockDim.x + threadIdx.x;   // over NT*DD/4
    if (i < NT * DD / 4) {
        float4 v = (i < NU * DD / 4) ? users[i] : items[i - NU * DD / 4];
        reinterpret_cast<float4*>(g_emb0)[i] = v;
        reinterpret_cast<float4*>(g_acc)[i]  = v;
    }
}

// zero the destination ping-pong buffer
__global__ void k_zero_dst(int src_is0) {
    int i = blockIdx.x * blockDim.x + threadIdx.x;
    if (i < NT * DD / 4) {
        float4* dst = reinterpret_cast<float4*>(src_is0 ? g_emb1 : g_emb0);
        dst[i] = make_float4(0.f, 0.f, 0.f, 0.f);
    }
}

// SpMM: dst[r] += w_e * src[c], 16 threads per edge, float4 each,
// vectorized global reduction (red.global.add.v4.f32, sm_90+)
__global__ void k_spmm(const int* __restrict__ row,
                       const int* __restrict__ col,
                       int src_is0) {
    int t = blockIdx.x * blockDim.x + threadIdx.x;   // EE*16 = 64M < 2^31
    if (t >= EE * 16) return;
    int e = t >> 4;
    int j = (t & 15) << 2;

    int r = __ldg(&row[e]);
    int c = __ldg(&col[e]);
    float w = g_dis[r] * g_dis[c];

    const float* src = src_is0 ? g_emb0 : g_emb1;
    float*       dst = src_is0 ? g_emb1 : g_emb0;

    float4 v = *reinterpret_cast<const float4*>(&src[c * DD + j]);
    if (w != 0.0f) {
        float ox = w * v.x, oy = w * v.y, oz = w * v.z, ow = w * v.w;
        asm volatile("red.global.add.v4.f32 [%0], {%1, %2, %3, %4};"
                     :: "l"(&dst[r * DD + j]),
                        "f"(ox), "f"(oy), "f"(oz), "f"(ow)
                     : "memory");
    }
}

// acc += dst
__global__ void k_acc(int src_is0) {
    int i = blockIdx.x * blockDim.x + threadIdx.x;
    if (i < NT * DD / 4) {
        const float4* dst = reinterpret_cast<const float4*>(src_is0 ? g_emb1 : g_emb0);
        float4* acc = reinterpret_cast<float4*>(g_acc);
        float4 d = dst[i];
        float4 a = acc[i];
        a.x += d.x; a.y += d.y; a.z += d.z; a.w += d.w;
        acc[i] = a;
    }
}

// out[b, 0:64] = 0.25*acc[uid[b]]; out[b, 64:128] = 0.25*acc[NU+iid[b]]
__global__ void k_gather(const int* __restrict__ uid,
                         const int* __restrict__ iid,
                         float4* __restrict__ out) {
    int t = blockIdx.x * blockDim.x + threadIdx.x;   // BB*32 threads
    if (t >= BB * 32) return;
    int b = t >> 5;
    int s = t & 31;                // 32 float4 per output row (128 floats)
    int node = (s < 16) ? __ldg(&uid[b]) : (NU + __ldg(&iid[b]));
    int j = (s & 15) << 2;
    float4 v = *reinterpret_cast<const float4*>(&g_acc[node * DD + j]);
    float4 o = make_float4(0.25f * v.x, 0.25f * v.y, 0.25f * v.z, 0.25f * v.w);
    out[b * 32 + s] = o;
}

extern "C" void kernel_launch(void* const* d_in, const int* in_sizes, int n_in,
                              void* d_out, int out_size) {
    const float* users = (const float*)d_in[0];
    const float* items = (const float*)d_in[1];
    const int*   erow  = (const int*)d_in[2];
    const int*   ecol  = (const int*)d_in[3];
    const int*   uid   = (const int*)d_in[4];
    const int*   iid   = (const int*)d_in[5];
    float4*      out   = (float4*)d_out;

    const int TB = 256;
    const int ND4 = NT * DD / 4;

    k_zero_deg<<<(NT + TB - 1) / TB, TB>>>();
    k_hist    <<<(EE + TB - 1) / TB, TB>>>(erow);
    k_dis     <<<(NT + TB - 1) / TB, TB>>>();
    k_init    <<<(ND4 + TB - 1) / TB, TB>>>((const float4*)users, (const float4*)items);

    int src_is0 = 1;
    for (int h = 0; h < KH; h++) {
        k_zero_dst<<<(ND4 + TB - 1) / TB, TB>>>(src_is0);
        long long spmm_threads = (long long)EE * 16;
        k_spmm    <<<(int)((spmm_threads + TB - 1) / TB), TB>>>(erow, ecol, src_is0);
        k_acc     <<<(ND4 + TB - 1) / TB, TB>>>(src_is0);
        src_is0 ^= 1;
    }

    k_gather<<<(BB * 32 + TB - 1) / TB, TB>>>(uid, iid, out);
}

// round 2
// speedup vs baseline: 2.8718x; 2.8718x over previous
#include <cuda_runtime.h>
#include <cuda_bf16.h>

#define NU 100000
#define NI 50000
#define NT 150000          // NU + NI
#define EE 4000000
#define DD 64
#define BB 4096

#define SCAN_B 1024
#define NBLK_SCAN ((NT + SCAN_B - 1) / SCAN_B)   // 147

// ---- scratch (device globals: allocation-free) ----
__device__ __align__(256) float g_e0[NT * DD];
__device__ __align__(256) float g_h1[NT * DD];
__device__ __align__(256) float g_h2[NT * DD];
__device__ __align__(256) float g_h3[NT * DD];
__device__ __align__(256) float g_dis[NT];
__device__ __align__(256) int   g_deg[NT];
__device__ __align__(256) int   g_rowptr[NT + 1];
__device__ __align__(256) int   g_cursor[NT];
__device__ __align__(256) int   g_bsum[NBLK_SCAN];
__device__ __align__(256) int2  g_colw[EE];      // {col, bits(w)}

__global__ void k_zero_deg() {
    int i = blockIdx.x * blockDim.x + threadIdx.x;
    if (i < NT) g_deg[i] = 0;
}

__global__ void k_hist(const int* __restrict__ row) {
    int e = blockIdx.x * blockDim.x + threadIdx.x;
    if (e < EE) atomicAdd(&g_deg[row[e]], 1);
}

__global__ void k_dis() {
    int i = blockIdx.x * blockDim.x + threadIdx.x;
    if (i < NT) {
        int d = g_deg[i];
        g_dis[i] = (d > 0) ? rsqrtf((float)d) : 0.0f;
    }
}

// ---- exclusive scan of deg -> rowptr (3 kernels) ----
__global__ void k_scan1() {
    __shared__ int sh[SCAN_B];
    int i = blockIdx.x * SCAN_B + threadIdx.x;
    int v = (i < NT) ? g_deg[i] : 0;
    sh[threadIdx.x] = v;
    __syncthreads();
    for (int off = 1; off < SCAN_B; off <<= 1) {
        int x = (threadIdx.x >= off) ? sh[threadIdx.x - off] : 0;
        __syncthreads();
        sh[threadIdx.x] += x;
        __syncthreads();
    }
    int incl = sh[threadIdx.x];
    if (i < NT) g_rowptr[i] = incl - v;           // exclusive, per-block
    if (threadIdx.x == SCAN_B - 1) g_bsum[blockIdx.x] = incl;
}

__global__ void k_scan2() {
    if (threadIdx.x == 0) {
        int run = 0;
        for (int b = 0; b < NBLK_SCAN; b++) {
            int t = g_bsum[b];
            g_bsum[b] = run;
            run += t;
        }
    }
}

__global__ void k_scan3() {
    int i = blockIdx.x * blockDim.x + threadIdx.x;
    if (i < NT) {
        int v = g_rowptr[i] + g_bsum[i / SCAN_B];
        g_rowptr[i] = v;
        g_cursor[i] = v;
        if (i == 0) g_rowptr[NT] = EE;
    }
}

// fill CSR: precompute edge weight, pack {col, w}
__global__ void k_fill(const int* __restrict__ row, const int* __restrict__ col) {
    int e = blockIdx.x * blockDim.x + threadIdx.x;
    if (e < EE) {
        int r = row[e];
        int c = col[e];
        float w = g_dis[r] * g_dis[c];
        int pos = atomicAdd(&g_cursor[r], 1);
        g_colw[pos] = make_int2(c, __float_as_int(w));
    }
}

// init e0 = concat(users, items)
__global__ void k_init(const float4* __restrict__ users,
                       const float4* __restrict__ items) {
    int i = blockIdx.x * blockDim.x + threadIdx.x;   // over NT*DD/4
    if (i < NT * DD / 4) {
        float4 v = (i < NU * DD / 4) ? users[i] : items[i - NU * DD / 4];
        reinterpret_cast<float4*>(g_e0)[i] = v;
    }
}

// CSR SpMM: 16 threads per row, float4 per thread, register accumulation.
// hop selects src/dst among {e0,h1,h2,h3}.
__global__ void __launch_bounds__(256) k_spmm(int hop) {
    int t = blockIdx.x * blockDim.x + threadIdx.x;
    int r = t >> 4;
    if (r >= NT) return;
    int lane = t & 15;

    const float* src = (hop == 0) ? g_e0 : (hop == 1) ? g_h1 : g_h2;
    float*       dst = (hop == 0) ? g_h1 : (hop == 1) ? g_h2 : g_h3;

    int beg = g_rowptr[r];
    int end = g_rowptr[r + 1];
    const int2* __restrict__ cw = g_colw;

    float4 s = make_float4(0.f, 0.f, 0.f, 0.f);
    int off = lane << 2;
    int i = beg;
    // 2-way unrolled for MLP
    for (; i + 1 < end; i += 2) {
        int2 p0 = __ldg(&cw[i]);
        int2 p1 = __ldg(&cw[i + 1]);
        float4 v0 = *reinterpret_cast<const float4*>(src + p0.x * DD + off);
        float4 v1 = *reinterpret_cast<const float4*>(src + p1.x * DD + off);
        float w0 = __int_as_float(p0.y);
        float w1 = __int_as_float(p1.y);
        s.x = fmaf(w0, v0.x, s.x); s.y = fmaf(w0, v0.y, s.y);
        s.z = fmaf(w0, v0.z, s.z); s.w = fmaf(w0, v0.w, s.w);
        s.x = fmaf(w1, v1.x, s.x); s.y = fmaf(w1, v1.y, s.y);
        s.z = fmaf(w1, v1.z, s.z); s.w = fmaf(w1, v1.w, s.w);
    }
    if (i < end) {
        int2 p = __ldg(&cw[i]);
        float4 v = *reinterpret_cast<const float4*>(src + p.x * DD + off);
        float w = __int_as_float(p.y);
        s.x = fmaf(w, v.x, s.x); s.y = fmaf(w, v.y, s.y);
        s.z = fmaf(w, v.z, s.z); s.w = fmaf(w, v.w, s.w);
    }
    *reinterpret_cast<float4*>(dst + r * DD + off) = s;
}

// out[b,0:64]=0.25*Σlayers[uid[b]]; out[b,64:128]=0.25*Σlayers[NU+iid[b]]
__global__ void k_gather(const int* __restrict__ uid,
                         const int* __restrict__ iid,
                         float4* __restrict__ out) {
    int t = blockIdx.x * blockDim.x + threadIdx.x;   // BB*32 threads
    if (t >= BB * 32) return;
    int b = t >> 5;
    int s = t & 31;
    int node = (s < 16) ? __ldg(&uid[b]) : (NU + __ldg(&iid[b]));
    int j = (s & 15) << 2;
    int idx = node * DD + j;
    float4 a = *reinterpret_cast<const float4*>(g_e0 + idx);
    float4 b1 = *reinterpret_cast<const float4*>(g_h1 + idx);
    float4 b2 = *reinterpret_cast<const float4*>(g_h2 + idx);
    float4 b3 = *reinterpret_cast<const float4*>(g_h3 + idx);
    float4 o;
    o.x = 0.25f * (a.x + b1.x + b2.x + b3.x);
    o.y = 0.25f * (a.y + b1.y + b2.y + b3.y);
    o.z = 0.25f * (a.z + b1.z + b2.z + b3.z);
    o.w = 0.25f * (a.w + b1.w + b2.w + b3.w);
    out[b * 32 + s] = o;
}

extern "C" void kernel_launch(void* const* d_in, const int* in_sizes, int n_in,
                              void* d_out, int out_size) {
    const float* users = (const float*)d_in[0];
    const float* items = (const float*)d_in[1];
    const int*   erow  = (const int*)d_in[2];
    const int*   ecol  = (const int*)d_in[3];
    const int*   uid   = (const int*)d_in[4];
    const int*   iid   = (const int*)d_in[5];
    float4*      out   = (float4*)d_out;

    const int TB = 256;
    const int ND4 = NT * DD / 4;

    k_zero_deg<<<(NT + TB - 1) / TB, TB>>>();
    k_hist    <<<(EE + TB - 1) / TB, TB>>>(erow);
    k_dis     <<<(NT + TB - 1) / TB, TB>>>();
    k_scan1   <<<NBLK_SCAN, SCAN_B>>>();
    k_scan2   <<<1, 32>>>();
    k_scan3   <<<(NT + TB - 1) / TB, TB>>>();
    k_fill    <<<(EE + TB - 1) / TB, TB>>>(erow, ecol);
    k_init    <<<(ND4 + TB - 1) / TB, TB>>>((const float4*)users, (const float4*)items);

    int spmm_threads = NT * 16;
    for (int hop = 0; hop < 3; hop++) {
        k_spmm<<<(spmm_threads + TB - 1) / TB, TB>>>(hop);
    }

    k_gather<<<(BB * 32 + TB - 1) / TB, TB>>>(uid, iid, out);
}

// round 3
// speedup vs baseline: 3.4039x; 1.1853x over previous
#include <cuda_runtime.h>
#include <cuda_fp16.h>
#include <cuda_bf16.h>

#define NU 100000
#define NI 50000
#define NT 150000          // NU + NI
#define EE 4000000
#define DD 64
#define BB 4096

#define SCAN_B 1024
#define NBLK_SCAN ((NT + SCAN_B - 1) / SCAN_B)   // 147

// ---- scratch (device globals: allocation-free) ----
__device__ __align__(256) float  g_e0[NT * DD];   // fp32 layer snapshots
__device__ __align__(256) float  g_h1[NT * DD];
__device__ __align__(256) float  g_h2[NT * DD];
__device__ __align__(256) float  g_h3[NT * DD];
__device__ __align__(256) __half g_m0[NT * DD];   // fp16 gather mirrors (hop sources)
__device__ __align__(256) __half g_m1[NT * DD];
__device__ __align__(256) __half g_m2[NT * DD];
__device__ __align__(256) float  g_dis[NT];
__device__ __align__(256) int    g_deg[NT];
__device__ __align__(256) int    g_rowptr[NT + 1];
__device__ __align__(256) int    g_cursor[NT];
__device__ __align__(256) int    g_bsum[NBLK_SCAN];
__device__ __align__(256) int2   g_colw[EE];      // {col, bits(w)}

__global__ void k_zero_deg() {
    int i = blockIdx.x * blockDim.x + threadIdx.x;
    if (i < NT) g_deg[i] = 0;
}

__global__ void k_hist(const int* __restrict__ row) {
    int e = blockIdx.x * blockDim.x + threadIdx.x;
    if (e < EE) atomicAdd(&g_deg[row[e]], 1);
}

__global__ void k_dis() {
    int i = blockIdx.x * blockDim.x + threadIdx.x;
    if (i < NT) {
        int d = g_deg[i];
        g_dis[i] = (d > 0) ? rsqrtf((float)d) : 0.0f;
    }
}

// ---- exclusive scan of deg -> rowptr ----
__global__ void k_scan1() {
    __shared__ int sh[SCAN_B];
    int i = blockIdx.x * SCAN_B + threadIdx.x;
    int v = (i < NT) ? g_deg[i] : 0;
    sh[threadIdx.x] = v;
    __syncthreads();
    for (int off = 1; off < SCAN_B; off <<= 1) {
        int x = (threadIdx.x >= off) ? sh[threadIdx.x - off] : 0;
        __syncthreads();
        sh[threadIdx.x] += x;
        __syncthreads();
    }
    int incl = sh[threadIdx.x];
    if (i < NT) g_rowptr[i] = incl - v;
    if (threadIdx.x == SCAN_B - 1) g_bsum[blockIdx.x] = incl;
}

__global__ void k_scan2() {
    if (threadIdx.x == 0) {
        int run = 0;
        for (int b = 0; b < NBLK_SCAN; b++) {
            int t = g_bsum[b];
            g_bsum[b] = run;
            run += t;
        }
    }
}

__global__ void k_scan3() {
    int i = blockIdx.x * blockDim.x + threadIdx.x;
    if (i < NT) {
        int v = g_rowptr[i] + g_bsum[i / SCAN_B];
        g_rowptr[i] = v;
        g_cursor[i] = v;
        if (i == 0) g_rowptr[NT] = EE;
    }
}

__global__ void k_fill(const int* __restrict__ row, const int* __restrict__ col) {
    int e = blockIdx.x * blockDim.x + threadIdx.x;
    if (e < EE) {
        int r = row[e];
        int c = col[e];
        float w = g_dis[r] * g_dis[c];
        int pos = atomicAdd(&g_cursor[r], 1);
        g_colw[pos] = make_int2(c, __float_as_int(w));
    }
}

__device__ __forceinline__ int2 pack_half4(float4 s) {
    __half2 p0 = __floats2half2_rn(s.x, s.y);
    __half2 p1 = __floats2half2_rn(s.z, s.w);
    return make_int2(*reinterpret_cast<int*>(&p0), *reinterpret_cast<int*>(&p1));
}

// init e0 = concat(users, items); also write fp16 mirror m0
__global__ void k_init(const float4* __restrict__ users,
                       const float4* __restrict__ items) {
    int i = blockIdx.x * blockDim.x + threadIdx.x;   // over NT*DD/4
    if (i < NT * DD / 4) {
        float4 v = (i < NU * DD / 4) ? users[i] : items[i - NU * DD / 4];
        reinterpret_cast<float4*>(g_e0)[i] = v;
        reinterpret_cast<int2*>(g_m0)[i] = pack_half4(v);
    }
}

// CSR SpMM: 16 threads/row. Gather from fp16 mirror (int2 = 4 halves / lane),
// accumulate fp32, store fp32 snapshot + (hops 0,1) fp16 mirror for next hop.
__global__ void __launch_bounds__(256) k_spmm(int hop) {
    int t = blockIdx.x * blockDim.x + threadIdx.x;
    int r = t >> 4;
    if (r >= NT) return;
    int lane = t & 15;

    const int2* __restrict__ srcm =
        (hop == 0) ? (const int2*)g_m0 : (hop == 1) ? (const int2*)g_m1 : (const int2*)g_m2;
    float* dst  = (hop == 0) ? g_h1 : (hop == 1) ? g_h2 : g_h3;
    int2*  dstm = (hop == 0) ? (int2*)g_m1 : (hop == 1) ? (int2*)g_m2 : (int2*)0;

    int beg = g_rowptr[r];
    int end = g_rowptr[r + 1];
    const int2* __restrict__ cw = g_colw;

    float4 s = make_float4(0.f, 0.f, 0.f, 0.f);
    int i = beg;
    for (; i + 1 < end; i += 2) {
        int2 p0 = __ldg(&cw[i]);
        int2 p1 = __ldg(&cw[i + 1]);
        int2 u0 = __ldg(&srcm[p0.x * 16 + lane]);
        int2 u1 = __ldg(&srcm[p1.x * 16 + lane]);
        float w0 = __int_as_float(p0.y);
        float w1 = __int_as_float(p1.y);
        float2 a0 = __half22float2(*reinterpret_cast<__half2*>(&u0.x));
        float2 b0 = __half22float2(*reinterpret_cast<__half2*>(&u0.y));
        float2 a1 = __half22float2(*reinterpret_cast<__half2*>(&u1.x));
        float2 b1 = __half22float2(*reinterpret_cast<__half2*>(&u1.y));
        s.x = fmaf(w0, a0.x, s.x); s.y = fmaf(w0, a0.y, s.y);
        s.z = fmaf(w0, b0.x, s.z); s.w = fmaf(w0, b0.y, s.w);
        s.x = fmaf(w1, a1.x, s.x); s.y = fmaf(w1, a1.y, s.y);
        s.z = fmaf(w1, b1.x, s.z); s.w = fmaf(w1, b1.y, s.w);
    }
    if (i < end) {
        int2 p = __ldg(&cw[i]);
        int2 u = __ldg(&srcm[p.x * 16 + lane]);
        float w = __int_as_float(p.y);
        float2 a = __half22float2(*reinterpret_cast<__half2*>(&u.x));
        float2 b = __half22float2(*reinterpret_cast<__half2*>(&u.y));
        s.x = fmaf(w, a.x, s.x); s.y = fmaf(w, a.y, s.y);
        s.z = fmaf(w, b.x, s.z); s.w = fmaf(w, b.y, s.w);
    }

    int base4 = r * 16 + lane;                       // float4 index within row grid
    reinterpret_cast<float4*>(dst)[base4] = s;
    if (dstm) dstm[base4] = pack_half4(s);
}

// out[b,0:64]=0.25*Σlayers[uid[b]]; out[b,64:128]=0.25*Σlayers[NU+iid[b]]
__global__ void k_gather(const int* __restrict__ uid,
                         const int* __restrict__ iid,
                         float4* __restrict__ out) {
    int t = blockIdx.x * blockDim.x + threadIdx.x;   // BB*32 threads
    if (t >= BB * 32) return;
    int b = t >> 5;
    int s = t & 31;
    int node = (s < 16) ? __ldg(&uid[b]) : (NU + __ldg(&iid[b]));
    int j = (s & 15) << 2;
    int idx = node * DD + j;
    float4 a  = *reinterpret_cast<const float4*>(g_e0 + idx);
    float4 b1 = *reinterpret_cast<const float4*>(g_h1 + idx);
    float4 b2 = *reinterpret_cast<const float4*>(g_h2 + idx);
    float4 b3 = *reinterpret_cast<const float4*>(g_h3 + idx);
    float4 o;
    o.x = 0.25f * (a.x + b1.x + b2.x + b3.x);
    o.y = 0.25f * (a.y + b1.y + b2.y + b3.y);
    o.z = 0.25f * (a.z + b1.z + b2.z + b3.z);
    o.w = 0.25f * (a.w + b1.w + b2.w + b3.w);
    out[b * 32 + s] = o;
}

extern "C" void kernel_launch(void* const* d_in, const int* in_sizes, int n_in,
                              void* d_out, int out_size) {
    const float* users = (const float*)d_in[0];
    const float* items = (const float*)d_in[1];
    const int*   erow  = (const int*)d_in[2];
    const int*   ecol  = (const int*)d_in[3];
    const int*   uid   = (const int*)d_in[4];
    const int*   iid   = (const int*)d_in[5];
    float4*      out   = (float4*)d_out;

    const int TB = 256;
    const int ND4 = NT * DD / 4;

    k_zero_deg<<<(NT + TB - 1) / TB, TB>>>();
    k_hist    <<<(EE + TB - 1) / TB, TB>>>(erow);
    k_dis     <<<(NT + TB - 1) / TB, TB>>>();
    k_scan1   <<<NBLK_SCAN, SCAN_B>>>();
    k_scan2   <<<1, 32>>>();
    k_scan3   <<<(NT + TB - 1) / TB, TB>>>();
    k_fill    <<<(EE + TB - 1) / TB, TB>>>(erow, ecol);
    k_init    <<<(ND4 + TB - 1) / TB, TB>>>((const float4*)users, (const float4*)items);

    int spmm_threads = NT * 16;
    for (int hop = 0; hop < 3; hop++) {
        k_spmm<<<(spmm_threads + TB - 1) / TB, TB>>>(hop);
    }

    k_gather<<<(BB * 32 + TB - 1) / TB, TB>>>(uid, iid, out);
}

// round 4
// speedup vs baseline: 3.7789x; 1.1102x over previous
#include <cuda_runtime.h>
#include <cuda_fp16.h>
#include <cuda_bf16.h>

#define NU 100000
#define NI 50000
#define NT 150000          // NU + NI
#define EE 4000000
#define DD 64
#define BB 4096

#define SCAN_B 1024
#define NBLK_SCAN ((NT + SCAN_B - 1) / SCAN_B)   // 147

// ---- scratch (device globals: allocation-free) ----
__device__ __align__(256) float  g_e0[NT * DD];   // fp32 layer snapshots
__device__ __align__(256) float  g_h1[NT * DD];
__device__ __align__(256) float  g_h2[NT * DD];
__device__ __align__(256) float  g_h3[NT * DD];
__device__ __align__(256) __half g_m0[NT * DD];   // fp16 mirrors, pre-scaled by dis[node]
__device__ __align__(256) __half g_m1[NT * DD];
__device__ __align__(256) __half g_m2[NT * DD];
__device__ __align__(256) float  g_dis[NT];
__device__ __align__(256) int    g_deg[NT];
__device__ __align__(256) int    g_rowptr[NT + 1];
__device__ __align__(256) int    g_cursor[NT];
__device__ __align__(256) int    g_bsum[NBLK_SCAN];
__device__ __align__(256) int    g_col[EE];       // CSR columns only (weights folded)

__global__ void k_zero_deg() {
    int i = blockIdx.x * blockDim.x + threadIdx.x;
    if (i < NT) g_deg[i] = 0;
}

__global__ void k_hist(const int* __restrict__ row) {
    int e = blockIdx.x * blockDim.x + threadIdx.x;
    if (e < EE) atomicAdd(&g_deg[row[e]], 1);
}

// scan step 1 + compute dis (deg already in hand)
__global__ void k_scan1() {
    __shared__ int sh[SCAN_B];
    int i = blockIdx.x * SCAN_B + threadIdx.x;
    int v = (i < NT) ? g_deg[i] : 0;
    if (i < NT) g_dis[i] = (v > 0) ? rsqrtf((float)v) : 0.0f;
    sh[threadIdx.x] = v;
    __syncthreads();
    for (int off = 1; off < SCAN_B; off <<= 1) {
        int x = (threadIdx.x >= off) ? sh[threadIdx.x - off] : 0;
        __syncthreads();
        sh[threadIdx.x] += x;
        __syncthreads();
    }
    int incl = sh[threadIdx.x];
    if (i < NT) g_rowptr[i] = incl - v;
    if (threadIdx.x == SCAN_B - 1) g_bsum[blockIdx.x] = incl;
}

__global__ void k_scan2() {
    if (threadIdx.x == 0) {
        int run = 0;
        for (int b = 0; b < NBLK_SCAN; b++) {
            int t = g_bsum[b];
            g_bsum[b] = run;
            run += t;
        }
    }
}

__global__ void k_scan3() {
    int i = blockIdx.x * blockDim.x + threadIdx.x;
    if (i < NT) {
        int v = g_rowptr[i] + g_bsum[i / SCAN_B];
        g_rowptr[i] = v;
        g_cursor[i] = v;
        if (i == 0) g_rowptr[NT] = EE;
    }
}

// fill CSR columns (no weights)
__global__ void k_fill(const int* __restrict__ row, const int* __restrict__ col) {
    int e = blockIdx.x * blockDim.x + threadIdx.x;
    if (e < EE) {
        int r = row[e];
        int pos = atomicAdd(&g_cursor[r], 1);
        g_col[pos] = col[e];
    }
}

__device__ __forceinline__ int2 pack_half4(float4 s) {
    __half2 p0 = __floats2half2_rn(s.x, s.y);
    __half2 p1 = __floats2half2_rn(s.z, s.w);
    return make_int2(*reinterpret_cast<int*>(&p0), *reinterpret_cast<int*>(&p1));
}

// init e0 = concat(users, items); mirror m0 = dis[node] * e0 (fp16)
__global__ void k_init(const float4* __restrict__ users,
                       const float4* __restrict__ items) {
    int i = blockIdx.x * blockDim.x + threadIdx.x;   // over NT*DD/4
    if (i < NT * DD / 4) {
        float4 v = (i < NU * DD / 4) ? users[i] : items[i - NU * DD / 4];
        reinterpret_cast<float4*>(g_e0)[i] = v;
        float d = g_dis[i >> 4];
        float4 m = make_float4(d * v.x, d * v.y, d * v.z, d * v.w);
        reinterpret_cast<int2*>(g_m0)[i] = pack_half4(m);
    }
}

// CSR SpMM: 16 threads/row; unweighted segment-sum of pre-scaled fp16 mirrors.
// h[r] = dis[r] * S; next mirror = dis[r] * h[r].
__global__ void __launch_bounds__(256) k_spmm(int hop) {
    int t = blockIdx.x * blockDim.x + threadIdx.x;
    int r = t >> 4;
    if (r >= NT) return;
    int lane = t & 15;

    const int2* __restrict__ srcm =
        (hop == 0) ? (const int2*)g_m0 : (hop == 1) ? (const int2*)g_m1 : (const int2*)g_m2;
    float* dst  = (hop == 0) ? g_h1 : (hop == 1) ? g_h2 : g_h3;
    int2*  dstm = (hop == 0) ? (int2*)g_m1 : (hop == 1) ? (int2*)g_m2 : (int2*)0;

    int beg = g_rowptr[r];
    int end = g_rowptr[r + 1];
    const int* __restrict__ col = g_col;

    float4 s = make_float4(0.f, 0.f, 0.f, 0.f);
    int i = beg;
    // 4-way unrolled for MLP on the col->gather dependent chain
    for (; i + 3 < end; i += 4) {
        int c0 = __ldg(&col[i]);
        int c1 = __ldg(&col[i + 1]);
        int c2 = __ldg(&col[i + 2]);
        int c3 = __ldg(&col[i + 3]);
        int2 u0 = __ldg(&srcm[c0 * 16 + lane]);
        int2 u1 = __ldg(&srcm[c1 * 16 + lane]);
        int2 u2 = __ldg(&srcm[c2 * 16 + lane]);
        int2 u3 = __ldg(&srcm[c3 * 16 + lane]);
        float2 a0 = __half22float2(*reinterpret_cast<__half2*>(&u0.x));
        float2 b0 = __half22float2(*reinterpret_cast<__half2*>(&u0.y));
        float2 a1 = __half22float2(*reinterpret_cast<__half2*>(&u1.x));
        float2 b1 = __half22float2(*reinterpret_cast<__half2*>(&u1.y));
        float2 a2 = __half22float2(*reinterpret_cast<__half2*>(&u2.x));
        float2 b2 = __half22float2(*reinterpret_cast<__half2*>(&u2.y));
        float2 a3 = __half22float2(*reinterpret_cast<__half2*>(&u3.x));
        float2 b3 = __half22float2(*reinterpret_cast<__half2*>(&u3.y));
        s.x += (a0.x + a1.x) + (a2.x + a3.x);
        s.y += (a0.y + a1.y) + (a2.y + a3.y);
        s.z += (b0.x + b1.x) + (b2.x + b3.x);
        s.w += (b0.y + b1.y) + (b2.y + b3.y);
    }
    for (; i < end; i++) {
        int c = __ldg(&col[i]);
        int2 u = __ldg(&srcm[c * 16 + lane]);
        float2 a = __half22float2(*reinterpret_cast<__half2*>(&u.x));
        float2 b = __half22float2(*reinterpret_cast<__half2*>(&u.y));
        s.x += a.x; s.y += a.y; s.z += b.x; s.w += b.y;
    }

    float dr = g_dis[r];
    float4 h = make_float4(dr * s.x, dr * s.y, dr * s.z, dr * s.w);
    int base4 = r * 16 + lane;
    reinterpret_cast<float4*>(dst)[base4] = h;
    if (dstm) {
        float4 m = make_float4(dr * h.x, dr * h.y, dr * h.z, dr * h.w);
        dstm[base4] = pack_half4(m);
    }
}

// out[b,0:64]=0.25*Σlayers[uid[b]]; out[b,64:128]=0.25*Σlayers[NU+iid[b]]
__global__ void k_gather(const int* __restrict__ uid,
                         const int* __restrict__ iid,
                         float4* __restrict__ out) {
    int t = blockIdx.x * blockDim.x + threadIdx.x;   // BB*32 threads
    if (t >= BB * 32) return;
    int b = t >> 5;
    int s = t & 31;
    int node = (s < 16) ? __ldg(&uid[b]) : (NU + __ldg(&iid[b]));
    int j = (s & 15) << 2;
    int idx = node * DD + j;
    float4 a  = *reinterpret_cast<const float4*>(g_e0 + idx);
    float4 b1 = *reinterpret_cast<const float4*>(g_h1 + idx);
    float4 b2 = *reinterpret_cast<const float4*>(g_h2 + idx);
    float4 b3 = *reinterpret_cast<const float4*>(g_h3 + idx);
    float4 o;
    o.x = 0.25f * (a.x + b1.x + b2.x + b3.x);
    o.y = 0.25f * (a.y + b1.y + b2.y + b3.y);
    o.z = 0.25f * (a.z + b1.z + b2.z + b3.z);
    o.w = 0.25f * (a.w + b1.w + b2.w + b3.w);
    out[b * 32 + s] = o;
}

extern "C" void kernel_launch(void* const* d_in, const int* in_sizes, int n_in,
                              void* d_out, int out_size) {
    const float* users = (const float*)d_in[0];
    const float* items = (const float*)d_in[1];
    const int*   erow  = (const int*)d_in[2];
    const int*   ecol  = (const int*)d_in[3];
    const int*   uid   = (const int*)d_in[4];
    const int*   iid   = (const int*)d_in[5];
    float4*      out   = (float4*)d_out;

    const int TB = 256;
    const int ND4 = NT * DD / 4;

    k_zero_deg<<<(NT + TB - 1) / TB, TB>>>();
    k_hist    <<<(EE + TB - 1) / TB, TB>>>(erow);
    k_scan1   <<<NBLK_SCAN, SCAN_B>>>();
    k_scan2   <<<1, 32>>>();
    k_scan3   <<<(NT + TB - 1) / TB, TB>>>();
    k_fill    <<<(EE + TB - 1) / TB, TB>>>(erow, ecol);
    k_init    <<<(ND4 + TB - 1) / TB, TB>>>((const float4*)users, (const float4*)items);

    int spmm_threads = NT * 16;
    for (int hop = 0; hop < 3; hop++) {
        k_spmm<<<(spmm_threads + TB - 1) / TB, TB>>>(hop);
    }

    k_gather<<<(BB * 32 + TB - 1) / TB, TB>>>(uid, iid, out);
}

// round 5
// speedup vs baseline: 3.9162x; 1.0363x over previous
#include <cuda_runtime.h>
#include <cuda_fp16.h>
#include <cuda_bf16.h>

#define NU 100000
#define NI 50000
#define NT 150000          // NU + NI
#define EE 4000000
#define DD 64
#define BB 4096

#define SCAN_B 1024
#define NBLK_SCAN ((NT + SCAN_B - 1) / SCAN_B)   // 147

// ---- scratch (device globals: allocation-free) ----
__device__ __align__(256) __half g_m0[NT * DD];   // fp16 mirrors (hops 0-2: dis-scaled)
__device__ __align__(256) __half g_m1[NT * DD];
__device__ __align__(256) __half g_m2[NT * DD];
__device__ __align__(256) __half g_m3[NT * DD];   // hop-3 result, UNscaled fp16
__device__ __align__(256) float  g_dis[NT];       // d^{-1/2}
__device__ __align__(256) float  g_dsq[NT];       // d^{+1/2}  (0 if deg==0)
__device__ __align__(256) int    g_deg[NT];
__device__ __align__(256) int    g_rowptr[NT + 1];
__device__ __align__(256) int    g_cursor[NT];
__device__ __align__(256) int    g_bsum[NBLK_SCAN];
__device__ __align__(256) int    g_col[EE];       // CSR columns (weights folded into mirrors)

__global__ void k_hist(const int* __restrict__ row) {
    int e = blockIdx.x * blockDim.x + threadIdx.x;
    if (e < EE) atomicAdd(&g_deg[row[e]], 1);
}

// scan step 1 + compute dis/dsq
__global__ void k_scan1() {
    __shared__ int sh[SCAN_B];
    int i = blockIdx.x * SCAN_B + threadIdx.x;
    int v = (i < NT) ? g_deg[i] : 0;
    if (i < NT) {
        g_dis[i] = (v > 0) ? rsqrtf((float)v) : 0.0f;
        g_dsq[i] = (v > 0) ? sqrtf((float)v)  : 0.0f;
    }
    sh[threadIdx.x] = v;
    __syncthreads();
    for (int off = 1; off < SCAN_B; off <<= 1) {
        int x = (threadIdx.x >= off) ? sh[threadIdx.x - off] : 0;
        __syncthreads();
        sh[threadIdx.x] += x;
        __syncthreads();
    }
    int incl = sh[threadIdx.x];
    if (i < NT) g_rowptr[i] = incl - v;
    if (threadIdx.x == SCAN_B - 1) g_bsum[blockIdx.x] = incl;
}

// parallel exclusive scan of the 147 block sums (single block)
__global__ void k_scan2() {
    __shared__ int sh[256];
    int t = threadIdx.x;
    int v = (t < NBLK_SCAN) ? g_bsum[t] : 0;
    sh[t] = v;
    __syncthreads();
    for (int off = 1; off < 256; off <<= 1) {
        int x = (t >= off) ? sh[t - off] : 0;
        __syncthreads();
        sh[t] += x;
        __syncthreads();
    }
    if (t < NBLK_SCAN) g_bsum[t] = sh[t] - v;   // exclusive
}

__global__ void k_scan3() {
    int i = blockIdx.x * blockDim.x + threadIdx.x;
    if (i < NT) {
        int v = g_rowptr[i] + g_bsum[i / SCAN_B];
        g_rowptr[i] = v;
        g_cursor[i] = v;
        if (i == 0) g_rowptr[NT] = EE;
    }
}

__global__ void k_fill(const int* __restrict__ row, const int* __restrict__ col) {
    int e = blockIdx.x * blockDim.x + threadIdx.x;
    if (e < EE) {
        int r = row[e];
        int pos = atomicAdd(&g_cursor[r], 1);
        g_col[pos] = col[e];
    }
}

__device__ __forceinline__ int2 pack_half4(float4 s) {
    __half2 p0 = __floats2half2_rn(s.x, s.y);
    __half2 p1 = __floats2half2_rn(s.z, s.w);
    return make_int2(*reinterpret_cast<int*>(&p0), *reinterpret_cast<int*>(&p1));
}

// m0 = dis[node] * concat(users, items)  (fp16); no fp32 snapshot stored
__global__ void k_init(const float4* __restrict__ users,
                       const float4* __restrict__ items) {
    int i = blockIdx.x * blockDim.x + threadIdx.x;   // over NT*DD/4
    if (i < NT * DD / 4) {
        float4 v = (i < NU * DD / 4) ? users[i] : items[i - NU * DD / 4];
        float d = g_dis[i >> 4];
        reinterpret_cast<int2*>(g_m0)[i] =
            pack_half4(make_float4(d * v.x, d * v.y, d * v.z, d * v.w));
    }
}

// CSR SpMM: 16 threads/row; unweighted segment-sum of pre-scaled fp16 mirrors.
// h = dis[r]*S.  hops 0,1: store dis[r]*h (scaled mirror). hop 2: store h.
__global__ void __launch_bounds__(256) k_spmm(int hop) {
    int t = blockIdx.x * blockDim.x + threadIdx.x;
    int r = t >> 4;
    if (r >= NT) return;
    int lane = t & 15;

    const int2* __restrict__ srcm =
        (hop == 0) ? (const int2*)g_m0 : (hop == 1) ? (const int2*)g_m1 : (const int2*)g_m2;
    int2* dstm =
        (hop == 0) ? (int2*)g_m1 : (hop == 1) ? (int2*)g_m2 : (int2*)g_m3;

    int beg = g_rowptr[r];
    int end = g_rowptr[r + 1];
    const int* __restrict__ col = g_col;

    float4 s = make_float4(0.f, 0.f, 0.f, 0.f);
    int i = beg;
    for (; i + 3 < end; i += 4) {
        int c0 = __ldg(&col[i]);
        int c1 = __ldg(&col[i + 1]);
        int c2 = __ldg(&col[i + 2]);
        int c3 = __ldg(&col[i + 3]);
        int2 u0 = __ldg(&srcm[c0 * 16 + lane]);
        int2 u1 = __ldg(&srcm[c1 * 16 + lane]);
        int2 u2 = __ldg(&srcm[c2 * 16 + lane]);
        int2 u3 = __ldg(&srcm[c3 * 16 + lane]);
        float2 a0 = __half22float2(*reinterpret_cast<__half2*>(&u0.x));
        float2 b0 = __half22float2(*reinterpret_cast<__half2*>(&u0.y));
        float2 a1 = __half22float2(*reinterpret_cast<__half2*>(&u1.x));
        float2 b1 = __half22float2(*reinterpret_cast<__half2*>(&u1.y));
        float2 a2 = __half22float2(*reinterpret_cast<__half2*>(&u2.x));
        float2 b2 = __half22float2(*reinterpret_cast<__half2*>(&u2.y));
        float2 a3 = __half22float2(*reinterpret_cast<__half2*>(&u3.x));
        float2 b3 = __half22float2(*reinterpret_cast<__half2*>(&u3.y));
        s.x += (a0.x + a1.x) + (a2.x + a3.x);
        s.y += (a0.y + a1.y) + (a2.y + a3.y);
        s.z += (b0.x + b1.x) + (b2.x + b3.x);
        s.w += (b0.y + b1.y) + (b2.y + b3.y);
    }
    for (; i < end; i++) {
        int c = __ldg(&col[i]);
        int2 u = __ldg(&srcm[c * 16 + lane]);
        float2 a = __half22float2(*reinterpret_cast<__half2*>(&u.x));
        float2 b = __half22float2(*reinterpret_cast<__half2*>(&u.y));
        s.x += a.x; s.y += a.y; s.z += b.x; s.w += b.y;
    }

    float dr = g_dis[r];
    float f = (hop == 2) ? dr : dr * dr;   // stored value = f * S
    reinterpret_cast<int2*>(dstm)[r * 16 + lane] =
        pack_half4(make_float4(f * s.x, f * s.y, f * s.z, f * s.w));
}

// out = 0.25 * (layer0 + m1*dsq + m2*dsq + h3)
__global__ void k_gather(const float* __restrict__ users,
                         const float* __restrict__ items,
                         const int* __restrict__ uid,
                         const int* __restrict__ iid,
                         float4* __restrict__ out) {
    int t = blockIdx.x * blockDim.x + threadIdx.x;   // BB*32 threads
    if (t >= BB * 32) return;
    int b = t >> 5;
    int s = t & 31;
    int node; const float* base0;
    if (s < 16) { int u = __ldg(&uid[b]); node = u;      base0 = users + u * DD; }
    else        { int v = __ldg(&iid[b]); node = NU + v; base0 = items + v * DD; }
    int j = (s & 15) << 2;
    int i4 = node * 16 + (j >> 2);

    float4 v0 = *reinterpret_cast<const float4*>(base0 + j);
    int2 u1 = reinterpret_cast<const int2*>(g_m1)[i4];
    int2 u2 = reinterpret_cast<const int2*>(g_m2)[i4];
    int2 u3 = reinterpret_cast<const int2*>(g_m3)[i4];
    float dq = g_dsq[node];

    float2 a1 = __half22float2(*reinterpret_cast<__half2*>(&u1.x));
    float2 c1 = __half22float2(*reinterpret_cast<__half2*>(&u1.y));
    float2 a2 = __half22float2(*reinterpret_cast<__half2*>(&u2.x));
    float2 c2 = __half22float2(*reinterpret_cast<__half2*>(&u2.y));
    float2 a3 = __half22float2(*reinterpret_cast<__half2*>(&u3.x));
    float2 c3 = __half22float2(*reinterpret_cast<__half2*>(&u3.y));

    float4 o;
    o.x = 0.25f * (v0.x + dq * (a1.x + a2.x) + a3.x);
    o.y = 0.25f * (v0.y + dq * (a1.y + a2.y) + a3.y);
    o.z = 0.25f * (v0.z + dq * (c1.x + c2.x) + c3.x);
    o.w = 0.25f * (v0.w + dq * (c1.y + c2.y) + c3.y);
    out[b * 32 + s] = o;
}

extern "C" void kernel_launch(void* const* d_in, const int* in_sizes, int n_in,
                              void* d_out, int out_size) {
    const float* users = (const float*)d_in[0];
    const float* items = (const float*)d_in[1];
    const int*   erow  = (const int*)d_in[2];
    const int*   ecol  = (const int*)d_in[3];
    const int*   uid   = (const int*)d_in[4];
    const int*   iid   = (const int*)d_in[5];
    float4*      out   = (float4*)d_out;

    const int TB = 256;
    const int ND4 = NT * DD / 4;

    void* degp = nullptr;
    cudaGetSymbolAddress(&degp, g_deg);
    cudaMemsetAsync(degp, 0, NT * sizeof(int));

    k_hist  <<<(EE + TB - 1) / TB, TB>>>(erow);
    k_scan1 <<<NBLK_SCAN, SCAN_B>>>();
    k_scan2 <<<1, 256>>>();
    k_scan3 <<<(NT + TB - 1) / TB, TB>>>();
    k_fill  <<<(EE + TB - 1) / TB, TB>>>(erow, ecol);
    k_init  <<<(ND4 + TB - 1) / TB, TB>>>((const float4*)users, (const float4*)items);

    int spmm_threads = NT * 16;
    for (int hop = 0; hop < 3; hop++) {
        k_spmm<<<(spmm_threads + TB - 1) / TB, TB>>>(hop);
    }

    k_gather<<<(BB * 32 + TB - 1) / TB, TB>>>(users, items, uid, iid, out);
}

// round 6
// speedup vs baseline: 4.4791x; 1.1437x over previous
#include <cuda_runtime.h>
#include <cuda_fp16.h>
#include <cuda_bf16.h>

#define NU 100000
#define NI 50000
#define NT 150000          // NU + NI
#define EE 4000000
#define DD 64
#define BB 4096

#define SCAN_B 1024
#define NBLK_SCAN ((NT + SCAN_B - 1) / SCAN_B)   // 147

// ---- scratch (device globals: allocation-free) ----
__device__ __align__(256) __half g_m0[NT * DD];   // fp16 scaled mirrors: m_k = dis^2 * S  (m0 = dis*e0)
__device__ __align__(256) __half g_m1[NT * DD];
__device__ __align__(256) __half g_m2[NT * DD];
__device__ __align__(256) float  g_dis[NT];       // d^{-1/2}
__device__ __align__(256) float  g_dsq[NT];       // d^{+1/2}  (0 if deg==0)
__device__ __align__(256) int    g_deg[NT];
__device__ __align__(256) int    g_rowptr[NT + 1];
__device__ __align__(256) int    g_cursor[NT];
__device__ __align__(256) int    g_bsum[NBLK_SCAN];
__device__ __align__(256) int    g_col[EE];       // CSR columns (weights folded into mirrors)

// histogram of edge rows, 4 edges/thread for atomic MLP
__global__ void k_hist(const int4* __restrict__ row4) {
    int i = blockIdx.x * blockDim.x + threadIdx.x;
    if (i < EE / 4) {
        int4 r = __ldg(&row4[i]);
        atomicAdd(&g_deg[r.x], 1);
        atomicAdd(&g_deg[r.y], 1);
        atomicAdd(&g_deg[r.z], 1);
        atomicAdd(&g_deg[r.w], 1);
    }
}

// scan step 1 + compute dis/dsq
__global__ void k_scan1() {
    __shared__ int sh[SCAN_B];
    int i = blockIdx.x * SCAN_B + threadIdx.x;
    int v = (i < NT) ? g_deg[i] : 0;
    if (i < NT) {
        g_dis[i] = (v > 0) ? rsqrtf((float)v) : 0.0f;
        g_dsq[i] = (v > 0) ? sqrtf((float)v)  : 0.0f;
    }
    sh[threadIdx.x] = v;
    __syncthreads();
    for (int off = 1; off < SCAN_B; off <<= 1) {
        int x = (threadIdx.x >= off) ? sh[threadIdx.x - off] : 0;
        __syncthreads();
        sh[threadIdx.x] += x;
        __syncthreads();
    }
    int incl = sh[threadIdx.x];
    if (i < NT) g_rowptr[i] = incl - v;
    if (threadIdx.x == SCAN_B - 1) g_bsum[blockIdx.x] = incl;
}

// parallel exclusive scan of the 147 block sums (single block)
__global__ void k_scan2() {
    __shared__ int sh[256];
    int t = threadIdx.x;
    int v = (t < NBLK_SCAN) ? g_bsum[t] : 0;
    sh[t] = v;
    __syncthreads();
    for (int off = 1; off < 256; off <<= 1) {
        int x = (t >= off) ? sh[t - off] : 0;
        __syncthreads();
        sh[t] += x;
        __syncthreads();
    }
    if (t < NBLK_SCAN) g_bsum[t] = sh[t] - v;   // exclusive
}

__device__ __forceinline__ int2 pack_half4(float4 s) {
    __half2 p0 = __floats2half2_rn(s.x, s.y);
    __half2 p1 = __floats2half2_rn(s.z, s.w);
    return make_int2(*reinterpret_cast<int*>(&p0), *reinterpret_cast<int*>(&p1));
}

// finalize rowptr/cursor AND build m0 = dis[node] * concat(users, items)
__global__ void k_scan3_init(const float4* __restrict__ users,
                             const float4* __restrict__ items) {
    int i = blockIdx.x * blockDim.x + threadIdx.x;
    if (i >= NT) return;
    int v = g_rowptr[i] + g_bsum[i / SCAN_B];
    g_rowptr[i] = v;
    g_cursor[i] = v;
    if (i == 0) g_rowptr[NT] = EE;

    float d = g_dis[i];
    const float4* src = (i < NU) ? (users + i * 16) : (items + (i - NU) * 16);
    int2* dst = reinterpret_cast<int2*>(g_m0) + i * 16;
    #pragma unroll
    for (int j = 0; j < 16; j++) {
        float4 x = __ldg(&src[j]);
        dst[j] = pack_half4(make_float4(d * x.x, d * x.y, d * x.z, d * x.w));
    }
}

// fill CSR columns, 4 edges/thread for atomic MLP
__global__ void k_fill(const int4* __restrict__ row4, const int4* __restrict__ col4) {
    int i = blockIdx.x * blockDim.x + threadIdx.x;
    if (i < EE / 4) {
        int4 r = __ldg(&row4[i]);
        int4 c = __ldg(&col4[i]);
        int p0 = atomicAdd(&g_cursor[r.x], 1);
        int p1 = atomicAdd(&g_cursor[r.y], 1);
        int p2 = atomicAdd(&g_cursor[r.z], 1);
        int p3 = atomicAdd(&g_cursor[r.w], 1);
        g_col[p0] = c.x;
        g_col[p1] = c.y;
        g_col[p2] = c.z;
        g_col[p3] = c.w;
    }
}

// CSR SpMM: 16 threads/row; unweighted segment-sum of scaled fp16 mirrors.
// Stores next scaled mirror: m_{k+1} = dis[r]^2 * S.
__global__ void __launch_bounds__(256) k_spmm(int hop) {
    int t = blockIdx.x * blockDim.x + threadIdx.x;
    int r = t >> 4;
    if (r >= NT) return;
    int lane = t & 15;

    const int2* __restrict__ srcm = (hop == 0) ? (const int2*)g_m0 : (const int2*)g_m1;
    int2* dstm                    = (hop == 0) ? (int2*)g_m1       : (int2*)g_m2;

    int beg = g_rowptr[r];
    int end = g_rowptr[r + 1];
    const int* __restrict__ col = g_col;

    float4 s = make_float4(0.f, 0.f, 0.f, 0.f);
    int i = beg;
    for (; i + 3 < end; i += 4) {
        int c0 = __ldg(&col[i]);
        int c1 = __ldg(&col[i + 1]);
        int c2 = __ldg(&col[i + 2]);
        int c3 = __ldg(&col[i + 3]);
        int2 u0 = __ldg(&srcm[c0 * 16 + lane]);
        int2 u1 = __ldg(&srcm[c1 * 16 + lane]);
        int2 u2 = __ldg(&srcm[c2 * 16 + lane]);
        int2 u3 = __ldg(&srcm[c3 * 16 + lane]);
        float2 a0 = __half22float2(*reinterpret_cast<__half2*>(&u0.x));
        float2 b0 = __half22float2(*reinterpret_cast<__half2*>(&u0.y));
        float2 a1 = __half22float2(*reinterpret_cast<__half2*>(&u1.x));
        float2 b1 = __half22float2(*reinterpret_cast<__half2*>(&u1.y));
        float2 a2 = __half22float2(*reinterpret_cast<__half2*>(&u2.x));
        float2 b2 = __half22float2(*reinterpret_cast<__half2*>(&u2.y));
        float2 a3 = __half22float2(*reinterpret_cast<__half2*>(&u3.x));
        float2 b3 = __half22float2(*reinterpret_cast<__half2*>(&u3.y));
        s.x += (a0.x + a1.x) + (a2.x + a3.x);
        s.y += (a0.y + a1.y) + (a2.y + a3.y);
        s.z += (b0.x + b1.x) + (b2.x + b3.x);
        s.w += (b0.y + b1.y) + (b2.y + b3.y);
    }
    for (; i < end; i++) {
        int c = __ldg(&col[i]);
        int2 u = __ldg(&srcm[c * 16 + lane]);
        float2 a = __half22float2(*reinterpret_cast<__half2*>(&u.x));
        float2 b = __half22float2(*reinterpret_cast<__half2*>(&u.y));
        s.x += a.x; s.y += a.y; s.z += b.x; s.w += b.y;
    }

    float dr = g_dis[r];
    float f = dr * dr;
    reinterpret_cast<int2*>(dstm)[r * 16 + lane] =
        pack_half4(make_float4(f * s.x, f * s.y, f * s.z, f * s.w));
}

// Fused hop-3 + gather: one warp per output slot (b, side).
// S = sum_{c in N(r)} m2[c];  out = 0.25*(e0[r] + dsq*(m1[r]+m2[r]) + dis[r]*S)
__global__ void __launch_bounds__(256) k_gather_fused(
        const float* __restrict__ users, const float* __restrict__ items,
        const int* __restrict__ uid, const int* __restrict__ iid,
        float2* __restrict__ out) {
    int t = blockIdx.x * blockDim.x + threadIdx.x;
    int slot = t >> 5;                 // 8192 slots
    if (slot >= BB * 2) return;
    int lane = t & 31;
    int b = slot >> 1, side = slot & 1;

    int node;
    const float2* e0;
    if (!side) { int u = __ldg(&uid[b]); node = u;      e0 = (const float2*)users + u * 32; }
    else       { int v = __ldg(&iid[b]); node = NU + v; e0 = (const float2*)items + v * 32; }

    int beg = g_rowptr[node];
    int end = g_rowptr[node + 1];
    const int* __restrict__ col = g_col;
    const __half2* __restrict__ m2h = (const __half2*)g_m2;

    float2 S = make_float2(0.f, 0.f);
    int i = beg;
    for (; i + 3 < end; i += 4) {
        int c0 = __ldg(&col[i]);
        int c1 = __ldg(&col[i + 1]);
        int c2 = __ldg(&col[i + 2]);
        int c3 = __ldg(&col[i + 3]);
        float2 x0 = __half22float2(__ldg(&m2h[c0 * 32 + lane]));
        float2 x1 = __half22float2(__ldg(&m2h[c1 * 32 + lane]));
        float2 x2 = __half22float2(__ldg(&m2h[c2 * 32 + lane]));
        float2 x3 = __half22float2(__ldg(&m2h[c3 * 32 + lane]));
        S.x += (x0.x + x1.x) + (x2.x + x3.x);
        S.y += (x0.y + x1.y) + (x2.y + x3.y);
    }
    for (; i < end; i++) {
        int c = __ldg(&col[i]);
        float2 x = __half22float2(__ldg(&m2h[c * 32 + lane]));
        S.x += x.x; S.y += x.y;
    }

    float dr = g_dis[node];
    float dq = g_dsq[node];
    float2 v0 = __ldg(&e0[lane]);
    float2 a1 = __half22float2(((const __half2*)g_m1)[node * 32 + lane]);
    float2 a2 = __half22float2(((const __half2*)g_m2)[node * 32 + lane]);

    float2 o;
    o.x = 0.25f * (v0.x + dq * (a1.x + a2.x) + dr * S.x);
    o.y = 0.25f * (v0.y + dq * (a1.y + a2.y) + dr * S.y);
    out[slot * 32 + lane] = o;         // = b*64 + side*32 + lane
}

extern "C" void kernel_launch(void* const* d_in, const int* in_sizes, int n_in,
                              void* d_out, int out_size) {
    const float* users = (const float*)d_in[0];
    const float* items = (const float*)d_in[1];
    const int*   erow  = (const int*)d_in[2];
    const int*   ecol  = (const int*)d_in[3];
    const int*   uid   = (const int*)d_in[4];
    const int*   iid   = (const int*)d_in[5];
    float2*      out   = (float2*)d_out;

    const int TB = 256;

    void* degp = nullptr;
    cudaGetSymbolAddress(&degp, g_deg);
    cudaMemsetAsync(degp, 0, NT * sizeof(int));

    k_hist       <<<(EE / 4 + TB - 1) / TB, TB>>>((const int4*)erow);
    k_scan1      <<<NBLK_SCAN, SCAN_B>>>();
    k_scan2      <<<1, 256>>>();
    k_scan3_init <<<(NT + TB - 1) / TB, TB>>>((const float4*)users, (const float4*)items);
    k_fill       <<<(EE / 4 + TB - 1) / TB, TB>>>((const int4*)erow, (const int4*)ecol);

    int spmm_threads = NT * 16;
    k_spmm<<<(spmm_threads + TB - 1) / TB, TB>>>(0);
    k_spmm<<<(spmm_threads + TB - 1) / TB, TB>>>(1);

    k_gather_fused<<<(BB * 2 * 32 + TB - 1) / TB, TB>>>(users, items, uid, iid, out);
}

// round 7
// speedup vs baseline: 4.6756x; 1.0439x over previous
#include <cuda_runtime.h>
#include <cuda_fp16.h>
#include <cuda_bf16.h>

#define NU 100000
#define NI 50000
#define NT 150000          // NU + NI
#define EE 4000000
#define DD 64
#define BB 4096

#define SCAN_B 1024
#define NBLK_SCAN ((NT + SCAN_B - 1) / SCAN_B)   // 147

// ---- scratch (device globals: allocation-free) ----
__device__ __align__(256) __half g_m0[NT * DD];   // fp16 scaled mirrors (m0 = dis*e0, m_{k+1} = dis^2*S)
__device__ __align__(256) __half g_m1[NT * DD];
__device__ __align__(256) __half g_m2[NT * DD];
__device__ __align__(256) float  g_dis[NT];       // d^{-1/2}
__device__ __align__(256) float  g_dsq[NT];       // d^{+1/2}  (0 if deg==0)
__device__ __align__(256) int    g_deg[NT];
__device__ __align__(256) int    g_rowptr[NT + 1];
__device__ __align__(256) int    g_cursor[NT];
__device__ __align__(256) int    g_bsum[NBLK_SCAN];
__device__ __align__(256) int    g_col[EE];       // CSR columns (weights folded into mirrors)

// histogram of edge rows, 8 edges/thread for atomic MLP
__global__ void k_hist(const int4* __restrict__ row4) {
    int i = (blockIdx.x * blockDim.x + threadIdx.x) * 2;
    if (i < EE / 4) {
        int4 r0 = __ldg(&row4[i]);
        int4 r1 = __ldg(&row4[i + 1]);
        atomicAdd(&g_deg[r0.x], 1);
        atomicAdd(&g_deg[r0.y], 1);
        atomicAdd(&g_deg[r0.z], 1);
        atomicAdd(&g_deg[r0.w], 1);
        atomicAdd(&g_deg[r1.x], 1);
        atomicAdd(&g_deg[r1.y], 1);
        atomicAdd(&g_deg[r1.z], 1);
        atomicAdd(&g_deg[r1.w], 1);
    }
}

// scan step 1 + compute dis/dsq
__global__ void k_scan1() {
    __shared__ int sh[SCAN_B];
    int i = blockIdx.x * SCAN_B + threadIdx.x;
    int v = (i < NT) ? g_deg[i] : 0;
    if (i < NT) {
        g_dis[i] = (v > 0) ? rsqrtf((float)v) : 0.0f;
        g_dsq[i] = (v > 0) ? sqrtf((float)v)  : 0.0f;
    }
    sh[threadIdx.x] = v;
    __syncthreads();
    for (int off = 1; off < SCAN_B; off <<= 1) {
        int x = (threadIdx.x >= off) ? sh[threadIdx.x - off] : 0;
        __syncthreads();
        sh[threadIdx.x] += x;
        __syncthreads();
    }
    int incl = sh[threadIdx.x];
    if (i < NT) g_rowptr[i] = incl - v;
    if (threadIdx.x == SCAN_B - 1) g_bsum[blockIdx.x] = incl;
}

// parallel exclusive scan of the 147 block sums (single block)
__global__ void k_scan2() {
    __shared__ int sh[256];
    int t = threadIdx.x;
    int v = (t < NBLK_SCAN) ? g_bsum[t] : 0;
    sh[t] = v;
    __syncthreads();
    for (int off = 1; off < 256; off <<= 1) {
        int x = (t >= off) ? sh[t - off] : 0;
        __syncthreads();
        sh[t] += x;
        __syncthreads();
    }
    if (t < NBLK_SCAN) g_bsum[t] = sh[t] - v;   // exclusive
}

__device__ __forceinline__ int2 pack_half4(float4 s) {
    __half2 p0 = __floats2half2_rn(s.x, s.y);
    __half2 p1 = __floats2half2_rn(s.z, s.w);
    return make_int2(*reinterpret_cast<int*>(&p0), *reinterpret_cast<int*>(&p1));
}

// COALESCED: one thread per float4 (NT*16 threads). lane==0 of each node's
// 16-thread group finalizes rowptr/cursor.
__global__ void k_scan3_init(const float4* __restrict__ users,
                             const float4* __restrict__ items) {
    int i = blockIdx.x * blockDim.x + threadIdx.x;   // over NT*16
    if (i >= NT * 16) return;
    int node = i >> 4;
    int lane = i & 15;

    if (lane == 0) {
        int v = g_rowptr[node] + g_bsum[node / SCAN_B];
        g_rowptr[node] = v;
        g_cursor[node] = v;
        if (node == 0) g_rowptr[NT] = EE;
    }

    float d = g_dis[node];
    float4 x = (node < NU) ? __ldg(&users[i - 0])             // users: i = node*16+lane
                           : __ldg(&items[i - NU * 16]);
    reinterpret_cast<int2*>(g_m0)[i] =
        pack_half4(make_float4(d * x.x, d * x.y, d * x.z, d * x.w));
}

// fill CSR columns, 4 edges/thread for atomic MLP
__global__ void k_fill(const int4* __restrict__ row4, const int4* __restrict__ col4) {
    int i = blockIdx.x * blockDim.x + threadIdx.x;
    if (i < EE / 4) {
        int4 r = __ldg(&row4[i]);
        int4 c = __ldg(&col4[i]);
        int p0 = atomicAdd(&g_cursor[r.x], 1);
        int p1 = atomicAdd(&g_cursor[r.y], 1);
        int p2 = atomicAdd(&g_cursor[r.z], 1);
        int p3 = atomicAdd(&g_cursor[r.w], 1);
        g_col[p0] = c.x;
        g_col[p1] = c.y;
        g_col[p2] = c.z;
        g_col[p3] = c.w;
    }
}

// CSR SpMM: 16 threads/row; unweighted segment-sum of scaled fp16 mirrors.
// Stores next scaled mirror: m_{k+1} = dis[r]^2 * S.
__global__ void __launch_bounds__(256) k_spmm(int hop) {
    int t = blockIdx.x * blockDim.x + threadIdx.x;
    int r = t >> 4;
    if (r >= NT) return;
    int lane = t & 15;

    const int2* __restrict__ srcm = (hop == 0) ? (const int2*)g_m0 : (const int2*)g_m1;
    int2* dstm                    = (hop == 0) ? (int2*)g_m1       : (int2*)g_m2;

    int beg = g_rowptr[r];
    int end = g_rowptr[r + 1];
    const int* __restrict__ col = g_col;

    float4 s = make_float4(0.f, 0.f, 0.f, 0.f);
    int i = beg;
    for (; i + 3 < end; i += 4) {
        int c0 = __ldg(&col[i]);
        int c1 = __ldg(&col[i + 1]);
        int c2 = __ldg(&col[i + 2]);
        int c3 = __ldg(&col[i + 3]);
        int2 u0 = __ldg(&srcm[c0 * 16 + lane]);
        int2 u1 = __ldg(&srcm[c1 * 16 + lane]);
        int2 u2 = __ldg(&srcm[c2 * 16 + lane]);
        int2 u3 = __ldg(&srcm[c3 * 16 + lane]);
        float2 a0 = __half22float2(*reinterpret_cast<__half2*>(&u0.x));
        float2 b0 = __half22float2(*reinterpret_cast<__half2*>(&u0.y));
        float2 a1 = __half22float2(*reinterpret_cast<__half2*>(&u1.x));
        float2 b1 = __half22float2(*reinterpret_cast<__half2*>(&u1.y));
        float2 a2 = __half22float2(*reinterpret_cast<__half2*>(&u2.x));
        float2 b2 = __half22float2(*reinterpret_cast<__half2*>(&u2.y));
        float2 a3 = __half22float2(*reinterpret_cast<__half2*>(&u3.x));
        float2 b3 = __half22float2(*reinterpret_cast<__half2*>(&u3.y));
        s.x += (a0.x + a1.x) + (a2.x + a3.x);
        s.y += (a0.y + a1.y) + (a2.y + a3.y);
        s.z += (b0.x + b1.x) + (b2.x + b3.x);
        s.w += (b0.y + b1.y) + (b2.y + b3.y);
    }
    for (; i < end; i++) {
        int c = __ldg(&col[i]);
        int2 u = __ldg(&srcm[c * 16 + lane]);
        float2 a = __half22float2(*reinterpret_cast<__half2*>(&u.x));
        float2 b = __half22float2(*reinterpret_cast<__half2*>(&u.y));
        s.x += a.x; s.y += a.y; s.z += b.x; s.w += b.y;
    }

    float dr = g_dis[r];
    float f = dr * dr;
    reinterpret_cast<int2*>(dstm)[r * 16 + lane] =
        pack_half4(make_float4(f * s.x, f * s.y, f * s.z, f * s.w));
}

// Fused hop-3 + gather: one warp per output slot (b, side).
// S = sum_{c in N(r)} m2[c];  out = 0.25*(e0[r] + dsq*(m1[r]+m2[r]) + dis[r]*S)
__global__ void __launch_bounds__(256) k_gather_fused(
        const float* __restrict__ users, const float* __restrict__ items,
        const int* __restrict__ uid, const int* __restrict__ iid,
        float2* __restrict__ out) {
    int t = blockIdx.x * blockDim.x + threadIdx.x;
    int slot = t >> 5;                 // 8192 slots
    if (slot >= BB * 2) return;
    int lane = t & 31;
    int b = slot >> 1, side = slot & 1;

    int node;
    const float2* e0;
    if (!side) { int u = __ldg(&uid[b]); node = u;      e0 = (const float2*)users + u * 32; }
    else       { int v = __ldg(&iid[b]); node = NU + v; e0 = (const float2*)items + v * 32; }

    int beg = g_rowptr[node];
    int end = g_rowptr[node + 1];
    const int* __restrict__ col = g_col;
    const __half2* __restrict__ m2h = (const __half2*)g_m2;

    float2 S = make_float2(0.f, 0.f);
    int i = beg;
    for (; i + 3 < end; i += 4) {
        int c0 = __ldg(&col[i]);
        int c1 = __ldg(&col[i + 1]);
        int c2 = __ldg(&col[i + 2]);
        int c3 = __ldg(&col[i + 3]);
        float2 x0 = __half22float2(__ldg(&m2h[c0 * 32 + lane]));
        float2 x1 = __half22float2(__ldg(&m2h[c1 * 32 + lane]));
        float2 x2 = __half22float2(__ldg(&m2h[c2 * 32 + lane]));
        float2 x3 = __half22float2(__ldg(&m2h[c3 * 32 + lane]));
        S.x += (x0.x + x1.x) + (x2.x + x3.x);
        S.y += (x0.y + x1.y) + (x2.y + x3.y);
    }
    for (; i < end; i++) {
        int c = __ldg(&col[i]);
        float2 x = __half22float2(__ldg(&m2h[c * 32 + lane]));
        S.x += x.x; S.y += x.y;
    }

    float dr = g_dis[node];
    float dq = g_dsq[node];
    float2 v0 = __ldg(&e0[lane]);
    float2 a1 = __half22float2(((const __half2*)g_m1)[node * 32 + lane]);
    float2 a2 = __half22float2(((const __half2*)g_m2)[node * 32 + lane]);

    float2 o;
    o.x = 0.25f * (v0.x + dq * (a1.x + a2.x) + dr * S.x);
    o.y = 0.25f * (v0.y + dq * (a1.y + a2.y) + dr * S.y);
    out[slot * 32 + lane] = o;         // = b*64 + side*32 + lane
}

extern "C" void kernel_launch(void* const* d_in, const int* in_sizes, int n_in,
                              void* d_out, int out_size) {
    const float* users = (const float*)d_in[0];
    const float* items = (const float*)d_in[1];
    const int*   erow  = (const int*)d_in[2];
    const int*   ecol  = (const int*)d_in[3];
    const int*   uid   = (const int*)d_in[4];
    const int*   iid   = (const int*)d_in[5];
    float2*      out   = (float2*)d_out;

    const int TB = 256;

    void* degp = nullptr;
    cudaGetSymbolAddress(&degp, g_deg);
    cudaMemsetAsync(degp, 0, NT * sizeof(int));

    k_hist       <<<(EE / 8 + TB - 1) / TB, TB>>>((const int4*)erow);
    k_scan1      <<<NBLK_SCAN, SCAN_B>>>();
    k_scan2      <<<1, 256>>>();
    k_scan3_init <<<(NT * 16 + TB - 1) / TB, TB>>>((const float4*)users, (const float4*)items);
    k_fill       <<<(EE / 4 + TB - 1) / TB, TB>>>((const int4*)erow, (const int4*)ecol);

    int spmm_threads = NT * 16;
    k_spmm<<<(spmm_threads + TB - 1) / TB, TB>>>(0);
    k_spmm<<<(spmm_threads + TB - 1) / TB, TB>>>(1);

    k_gather_fused<<<(BB * 2 * 32 + TB - 1) / TB, TB>>>(users, items, uid, iid, out);
}

// round 8
// speedup vs baseline: 4.8060x; 1.0279x over previous
#include <cuda_runtime.h>
#include <cuda_fp16.h>
#include <cuda_bf16.h>

#define NU 100000
#define NI 50000
#define NT 150000          // NU + NI
#define EE 4000000
#define DD 64
#define BB 4096

#define SCAN_B 1024
#define NBLK_SCAN ((NT + SCAN_B - 1) / SCAN_B)   // 147

#define TB 256
#define FILL_BLOCKS ((EE / 4 + TB - 1) / TB)      // 3907
#define INIT_BLOCKS ((NT * 16 + TB - 1) / TB)     // 9375

// ---- scratch (device globals: allocation-free) ----
__device__ __align__(256) __half g_m0[NT * DD];   // fp16 scaled mirrors (m0 = dis*e0, m_{k+1} = dis^2*S)
__device__ __align__(256) __half g_m1[NT * DD];
__device__ __align__(256) __half g_m2[NT * DD];
__device__ __align__(256) float  g_dis[NT];       // d^{-1/2}
__device__ __align__(256) float  g_dsq[NT];       // d^{+1/2}  (0 if deg==0)
__device__ __align__(256) int    g_deg[NT];
__device__ __align__(256) int    g_rowptr[NT + 1];
__device__ __align__(256) int    g_cursor[NT];
__device__ __align__(256) int    g_bsum[NBLK_SCAN];
__device__ __align__(256) int    g_col[EE];       // CSR columns (weights folded into mirrors)

// histogram of edge rows, 8 edges/thread for atomic MLP
__global__ void k_hist(const int4* __restrict__ row4) {
    int i = (blockIdx.x * blockDim.x + threadIdx.x) * 2;
    if (i < EE / 4) {
        int4 r0 = __ldg(&row4[i]);
        int4 r1 = __ldg(&row4[i + 1]);
        atomicAdd(&g_deg[r0.x], 1);
        atomicAdd(&g_deg[r0.y], 1);
        atomicAdd(&g_deg[r0.z], 1);
        atomicAdd(&g_deg[r0.w], 1);
        atomicAdd(&g_deg[r1.x], 1);
        atomicAdd(&g_deg[r1.y], 1);
        atomicAdd(&g_deg[r1.z], 1);
        atomicAdd(&g_deg[r1.w], 1);
    }
}

// scan step 1 + compute dis/dsq
__global__ void k_scan1() {
    __shared__ int sh[SCAN_B];
    int i = blockIdx.x * SCAN_B + threadIdx.x;
    int v = (i < NT) ? g_deg[i] : 0;
    if (i < NT) {
        g_dis[i] = (v > 0) ? rsqrtf((float)v) : 0.0f;
        g_dsq[i] = (v > 0) ? sqrtf((float)v)  : 0.0f;
    }
    sh[threadIdx.x] = v;
    __syncthreads();
    for (int off = 1; off < SCAN_B; off <<= 1) {
        int x = (threadIdx.x >= off) ? sh[threadIdx.x - off] : 0;
        __syncthreads();
        sh[threadIdx.x] += x;
        __syncthreads();
    }
    int incl = sh[threadIdx.x];
    if (i < NT) g_rowptr[i] = incl - v;
    if (threadIdx.x == SCAN_B - 1) g_bsum[blockIdx.x] = incl;
}

// parallel exclusive scan of the 147 block sums (single block)
__global__ void k_scan2() {
    __shared__ int sh[256];
    int t = threadIdx.x;
    int v = (t < NBLK_SCAN) ? g_bsum[t] : 0;
    sh[t] = v;
    __syncthreads();
    for (int off = 1; off < 256; off <<= 1) {
        int x = (t >= off) ? sh[t - off] : 0;
        __syncthreads();
        sh[t] += x;
        __syncthreads();
    }
    if (t < NBLK_SCAN) g_bsum[t] = sh[t] - v;   // exclusive
}

// finalize rowptr + cursor (small, fast)
__global__ void k_scan3() {
    int i = blockIdx.x * blockDim.x + threadIdx.x;
    if (i < NT) {
        int v = g_rowptr[i] + g_bsum[i / SCAN_B];
        g_rowptr[i] = v;
        g_cursor[i] = v;
        if (i == 0) g_rowptr[NT] = EE;
    }
}

__device__ __forceinline__ int2 pack_half4(float4 s) {
    __half2 p0 = __floats2half2_rn(s.x, s.y);
    __half2 p1 = __floats2half2_rn(s.z, s.w);
    return make_int2(*reinterpret_cast<int*>(&p0), *reinterpret_cast<int*>(&p1));
}

// Fused CSR-fill + m0-init: disjoint block ranges, co-resident on SMs.
// Fill is atomic/scatter latency-bound; init is DRAM-stream-bound -> overlap.
__global__ void __launch_bounds__(256) k_fill_init(
        const int4* __restrict__ row4, const int4* __restrict__ col4,
        const float4* __restrict__ users, const float4* __restrict__ items) {
    int b = blockIdx.x;
    if (b < FILL_BLOCKS) {
        // ---- CSR fill: 4 edges/thread ----
        int i = b * blockDim.x + threadIdx.x;
        if (i < EE / 4) {
            int4 r = __ldg(&row4[i]);
            int4 c = __ldg(&col4[i]);
            int p0 = atomicAdd(&g_cursor[r.x], 1);
            int p1 = atomicAdd(&g_cursor[r.y], 1);
            int p2 = atomicAdd(&g_cursor[r.z], 1);
            int p3 = atomicAdd(&g_cursor[r.w], 1);
            g_col[p0] = c.x;
            g_col[p1] = c.y;
            g_col[p2] = c.z;
            g_col[p3] = c.w;
        }
    } else {
        // ---- m0 init: one thread per float4, coalesced ----
        int i = (b - FILL_BLOCKS) * blockDim.x + threadIdx.x;   // over NT*16
        if (i < NT * 16) {
            int node = i >> 4;
            float d = g_dis[node];
            float4 x = (node < NU) ? __ldg(&users[i])
                                   : __ldg(&items[i - NU * 16]);
            reinterpret_cast<int2*>(g_m0)[i] =
                pack_half4(make_float4(d * x.x, d * x.y, d * x.z, d * x.w));
        }
    }
}

// CSR SpMM: 16 threads/row; unweighted segment-sum of scaled fp16 mirrors.
// Stores next scaled mirror: m_{k+1} = dis[r]^2 * S.
__global__ void __launch_bounds__(256) k_spmm(int hop) {
    int t = blockIdx.x * blockDim.x + threadIdx.x;
    int r = t >> 4;
    if (r >= NT) return;
    int lane = t & 15;

    const int2* __restrict__ srcm = (hop == 0) ? (const int2*)g_m0 : (const int2*)g_m1;
    int2* dstm                    = (hop == 0) ? (int2*)g_m1       : (int2*)g_m2;

    int beg = g_rowptr[r];
    int end = g_rowptr[r + 1];
    const int* __restrict__ col = g_col;

    float4 s = make_float4(0.f, 0.f, 0.f, 0.f);
    int i = beg;
    for (; i + 3 < end; i += 4) {
        int c0 = __ldg(&col[i]);
        int c1 = __ldg(&col[i + 1]);
        int c2 = __ldg(&col[i + 2]);
        int c3 = __ldg(&col[i + 3]);
        int2 u0 = __ldg(&srcm[c0 * 16 + lane]);
        int2 u1 = __ldg(&srcm[c1 * 16 + lane]);
        int2 u2 = __ldg(&srcm[c2 * 16 + lane]);
        int2 u3 = __ldg(&srcm[c3 * 16 + lane]);
        float2 a0 = __half22float2(*reinterpret_cast<__half2*>(&u0.x));
        float2 b0 = __half22float2(*reinterpret_cast<__half2*>(&u0.y));
        float2 a1 = __half22float2(*reinterpret_cast<__half2*>(&u1.x));
        float2 b1 = __half22float2(*reinterpret_cast<__half2*>(&u1.y));
        float2 a2 = __half22float2(*reinterpret_cast<__half2*>(&u2.x));
        float2 b2 = __half22float2(*reinterpret_cast<__half2*>(&u2.y));
        float2 a3 = __half22float2(*reinterpret_cast<__half2*>(&u3.x));
        float2 b3 = __half22float2(*reinterpret_cast<__half2*>(&u3.y));
        s.x += (a0.x + a1.x) + (a2.x + a3.x);
        s.y += (a0.y + a1.y) + (a2.y + a3.y);
        s.z += (b0.x + b1.x) + (b2.x + b3.x);
        s.w += (b0.y + b1.y) + (b2.y + b3.y);
    }
    for (; i < end; i++) {
        int c = __ldg(&col[i]);
        int2 u = __ldg(&srcm[c * 16 + lane]);
        float2 a = __half22float2(*reinterpret_cast<__half2*>(&u.x));
        float2 b = __half22float2(*reinterpret_cast<__half2*>(&u.y));
        s.x += a.x; s.y += a.y; s.z += b.x; s.w += b.y;
    }

    float dr = g_dis[r];
    float f = dr * dr;
    reinterpret_cast<int2*>(dstm)[r * 16 + lane] =
        pack_half4(make_float4(f * s.x, f * s.y, f * s.z, f * s.w));
}

// Fused hop-3 + gather: one warp per output slot (b, side).
// S = sum_{c in N(r)} m2[c];  out = 0.25*(e0[r] + dsq*(m1[r]+m2[r]) + dis[r]*S)
__global__ void __launch_bounds__(256) k_gather_fused(
        const float* __restrict__ users, const float* __restrict__ items,
        const int* __restrict__ uid, const int* __restrict__ iid,
        float2* __restrict__ out) {
    int t = blockIdx.x * blockDim.x + threadIdx.x;
    int slot = t >> 5;                 // 8192 slots
    if (slot >= BB * 2) return;
    int lane = t & 31;
    int b = slot >> 1, side = slot & 1;

    int node;
    const float2* e0;
    if (!side) { int u = __ldg(&uid[b]); node = u;      e0 = (const float2*)users + u * 32; }
    else       { int v = __ldg(&iid[b]); node = NU + v; e0 = (const float2*)items + v * 32; }

    int beg = g_rowptr[node];
    int end = g_rowptr[node + 1];
    const int* __restrict__ col = g_col;
    const __half2* __restrict__ m2h = (const __half2*)g_m2;

    float2 S = make_float2(0.f, 0.f);
    int i = beg;
    for (; i + 3 < end; i += 4) {
        int c0 = __ldg(&col[i]);
        int c1 = __ldg(&col[i + 1]);
        int c2 = __ldg(&col[i + 2]);
        int c3 = __ldg(&col[i + 3]);
        float2 x0 = __half22float2(__ldg(&m2h[c0 * 32 + lane]));
        float2 x1 = __half22float2(__ldg(&m2h[c1 * 32 + lane]));
        float2 x2 = __half22float2(__ldg(&m2h[c2 * 32 + lane]));
        float2 x3 = __half22float2(__ldg(&m2h[c3 * 32 + lane]));
        S.x += (x0.x + x1.x) + (x2.x + x3.x);
        S.y += (x0.y + x1.y) + (x2.y + x3.y);
    }
    for (; i < end; i++) {
        int c = __ldg(&col[i]);
        float2 x = __half22float2(__ldg(&m2h[c * 32 + lane]));
        S.x += x.x; S.y += x.y;
    }

    float dr = g_dis[node];
    float dq = g_dsq[node];
    float2 v0 = __ldg(&e0[lane]);
    float2 a1 = __half22float2(((const __half2*)g_m1)[node * 32 + lane]);
    float2 a2 = __half22float2(((const __half2*)g_m2)[node * 32 + lane]);

    float2 o;
    o.x = 0.25f * (v0.x + dq * (a1.x + a2.x) + dr * S.x);
    o.y = 0.25f * (v0.y + dq * (a1.y + a2.y) + dr * S.y);
    out[slot * 32 + lane] = o;         // = b*64 + side*32 + lane
}

extern "C" void kernel_launch(void* const* d_in, const int* in_sizes, int n_in,
                              void* d_out, int out_size) {
    const float* users = (const float*)d_in[0];
    const float* items = (const float*)d_in[1];
    const int*   erow  = (const int*)d_in[2];
    const int*   ecol  = (const int*)d_in[3];
    const int*   uid   = (const int*)d_in[4];
    const int*   iid   = (const int*)d_in[5];
    float2*      out   = (float2*)d_out;

    void* degp = nullptr;
    cudaGetSymbolAddress(&degp, g_deg);
    cudaMemsetAsync(degp, 0, NT * sizeof(int));

    k_hist  <<<(EE / 8 + TB - 1) / TB, TB>>>((const int4*)erow);
    k_scan1 <<<NBLK_SCAN, SCAN_B>>>();
    k_scan2 <<<1, 256>>>();
    k_scan3 <<<(NT + TB - 1) / TB, TB>>>();
    k_fill_init<<<FILL_BLOCKS + INIT_BLOCKS, TB>>>(
        (const int4*)erow, (const int4*)ecol,
        (const float4*)users, (const float4*)items);

    int spmm_threads = NT * 16;
    k_spmm<<<(spmm_threads + TB - 1) / TB, TB>>>(0);
    k_spmm<<<(spmm_threads + TB - 1) / TB, TB>>>(1);

    k_gather_fused<<<(BB * 2 * 32 + TB - 1) / TB, TB>>>(users, items, uid, iid, out);
}